// round 10
// baseline (speedup 1.0000x reference)
#include <cuda_runtime.h>
#include <cuda_bf16.h>
#include <cstdint>
#include <math.h>

#define CC 32
#define II 32
#define TT 40
#define RR 36
#define DD 1024
#define MM (CC*II*TT)     /* 40960 */
#define KK 2048
#define PITCH 40          /* bf16 elems per smem row (32 data + 8 pad) */

// ---------------- device scratch (no cudaMalloc allowed) ----------------
__device__ float g_wc[(size_t)MM*DD];                 // weightedContext fp32
__device__ float g_q1[(size_t)MM*DD];                 // updated query
__device__ __nv_bfloat16 g_cat[(size_t)MM*KK];        // [query | wc] bf16
__device__ __nv_bfloat16 g_WtL[(size_t)DD*KK];        // W_lin^T  [n][k]
__device__ __nv_bfloat16 g_WtG[(size_t)DD*KK];        // W_gate^T [n][k]

// ---------------- helpers ----------------
__device__ __forceinline__ uint32_t smem_u32(const void* p) {
    uint32_t a;
    asm("{ .reg .u64 t; cvta.to.shared.u64 t, %1; cvt.u32.u64 %0, t; }" : "=r"(a) : "l"(p));
    return a;
}
__device__ __forceinline__ void cpa16(uint32_t d, const void* s) {
    asm volatile("cp.async.cg.shared.global [%0], [%1], 16;" :: "r"(d), "l"(s));
}
__device__ __forceinline__ void cpa_commit() { asm volatile("cp.async.commit_group;" ::: "memory"); }
__device__ __forceinline__ void cpa_wait0()  { asm volatile("cp.async.wait_group 0;" ::: "memory"); }

#define MMA16816(d, a, b) \
  asm volatile("mma.sync.aligned.m16n8k16.row.col.f32.bf16.bf16.f32 " \
    "{%0,%1,%2,%3}, {%4,%5,%6,%7}, {%8,%9}, {%0,%1,%2,%3};" \
    : "+f"((d)[0]), "+f"((d)[1]), "+f"((d)[2]), "+f"((d)[3]) \
    : "r"((a)[0]), "r"((a)[1]), "r"((a)[2]), "r"((a)[3]), "r"((b)[0]), "r"((b)[1]))

// ---------------- prep: W^T -> bf16 ----------------
__global__ void prep_wt(const float* __restrict__ W, int which) {
    __shared__ float tile[32][33];
    __nv_bfloat16* Wt = which ? g_WtG : g_WtL;
    int n0 = blockIdx.x * 32;   // 32 tiles
    int k0 = blockIdx.y * 32;   // 64 tiles
    int tx = threadIdx.x, ty = threadIdx.y;  // (32, 8)
    #pragma unroll
    for (int j = 0; j < 4; j++)
        tile[ty + j*8][tx] = W[(size_t)(k0 + ty + j*8) * DD + n0 + tx];
    __syncthreads();
    #pragma unroll
    for (int j = 0; j < 4; j++)
        Wt[(size_t)(n0 + ty + j*8) * KK + k0 + tx] =
            __float2bfloat16(tile[tx][ty + j*8]);
}

// ---------------- prep: cat left half = broadcast caption (bf16) ----------------
__global__ void prep_catL(const float* __restrict__ cap) {
    size_t idx = (size_t)blockIdx.x * 256 + threadIdx.x;   // f4 index in [0, MM*256)
    int m  = (int)(idx >> 8);
    int dv = (int)(idx & 255);
    int c = m / (II*TT), t = m % TT;
    float4 v = reinterpret_cast<const float4*>(cap)[((size_t)(c*TT + t) << 8) + dv];
    __nv_bfloat162 lo = __floats2bfloat162_rn(v.x, v.y);
    __nv_bfloat162 hi = __floats2bfloat162_rn(v.z, v.w);
    __nv_bfloat162* dst = reinterpret_cast<__nv_bfloat162*>(g_cat + (size_t)m*KK + (size_t)dv*4);
    dst[0] = lo; dst[1] = hi;
}

// ---------------- fused attention step ----------------
// attn = leaky(ctx @ q^T); l2norm over t; softmax_r(9*attn^T); wc = attn @ ctx
__global__ __launch_bounds__(256)
void attn_kernel(const float* __restrict__ img, const float* __restrict__ cap, int iter) {
    extern __shared__ float sm[];
    float4* img4 = reinterpret_cast<float4*>(sm);   // 36*256 float4
    float* attn  = sm + RR*DD;                      // [36][40]  (r-major)
    float* attn2 = attn + RR*TT;                    // [40][36]  (t-major, softmaxed)
    int tid = threadIdx.x, lane = tid & 31, w = tid >> 5;
    int pair = blockIdx.x, c = pair >> 5, i = pair & 31;

    // load image region tile into smem
    const float4* imgv = reinterpret_cast<const float4*>(img) + (size_t)i * RR * 256;
    #pragma unroll
    for (int j = 0; j < 36; j++)
        img4[j*256 + tid] = imgv[j*256 + tid];
    __syncthreads();

    // phase B: dot products, Q rows in registers (2 t-rows per pass)
    const float4* qv = iter ? reinterpret_cast<const float4*>(g_q1)
                            : reinterpret_cast<const float4*>(cap);
    for (int base = 0; base < 48; base += 16) {
        int tA = base + w;
        int tB = base + 8 + w;
        bool hasB = (base < 32);
        int rA = iter ? (pair*TT + tA) : (c*TT + tA);
        size_t qa = (size_t)rA * 256;
        float4 Qa[8], Qb[8];
        #pragma unroll
        for (int j = 0; j < 8; j++) Qa[j] = qv[qa + j*32 + lane];
        if (hasB) {
            int rB = iter ? (pair*TT + tB) : (c*TT + tB);
            size_t qb = (size_t)rB * 256;
            #pragma unroll
            for (int j = 0; j < 8; j++) Qb[j] = qv[qb + j*32 + lane];
        }
        for (int r = 0; r < RR; r++) {
            float pa = 0.f, pb = 0.f;
            #pragma unroll
            for (int j = 0; j < 8; j++) {
                float4 v = img4[r*256 + j*32 + lane];
                pa += v.x*Qa[j].x + v.y*Qa[j].y + v.z*Qa[j].z + v.w*Qa[j].w;
                if (hasB) pb += v.x*Qb[j].x + v.y*Qb[j].y + v.z*Qb[j].z + v.w*Qb[j].w;
            }
            #pragma unroll
            for (int o = 16; o; o >>= 1) {
                pa += __shfl_xor_sync(0xffffffffu, pa, o);
                pb += __shfl_xor_sync(0xffffffffu, pb, o);
            }
            if (lane == 0) {
                attn[r*TT + tA] = pa;
                if (hasB) attn[r*TT + tB] = pb;
            }
        }
    }
    __syncthreads();

    // phase C: leaky relu + l2norm over t (per r)
    if (tid < RR) {
        float s = 0.f;
        #pragma unroll 8
        for (int t = 0; t < TT; t++) {
            float v = attn[tid*TT + t];
            v = (v > 0.f) ? v : 0.1f * v;
            attn[tid*TT + t] = v;
            s += v * v;
        }
        float inv = 1.f / (sqrtf(s) + 1e-8f);
        #pragma unroll 8
        for (int t = 0; t < TT; t++) attn[tid*TT + t] *= inv;
    }
    __syncthreads();

    // phase D: softmax over r (per t), temperature 9
    if (tid < TT) {
        float mx = -1e30f;
        for (int r = 0; r < RR; r++) mx = fmaxf(mx, attn[r*TT + tid]);
        float s = 0.f;
        for (int r = 0; r < RR; r++) {
            float e = expf(9.0f * (attn[r*TT + tid] - mx));
            attn2[tid*RR + r] = e;
            s += e;
        }
        float inv = 1.f / s;
        for (int r = 0; r < RR; r++) attn2[tid*RR + r] *= inv;
    }
    __syncthreads();

    // phase E: wc[t][d] = sum_r attn2[t][r] * img[r][d]; write fp32 + bf16(cat right)
    for (int tb = 0; tb < 5; tb++) {
        float4 acc[8];
        #pragma unroll
        for (int j = 0; j < 8; j++) acc[j] = make_float4(0.f, 0.f, 0.f, 0.f);
        for (int r = 0; r < RR; r++) {
            float4 v = img4[r*256 + tid];
            #pragma unroll
            for (int j = 0; j < 8; j++) {
                float a = attn2[(tb*8 + j)*RR + r];
                acc[j].x += v.x*a; acc[j].y += v.y*a;
                acc[j].z += v.z*a; acc[j].w += v.w*a;
            }
        }
        #pragma unroll
        for (int j = 0; j < 8; j++) {
            int t = tb*8 + j;
            size_t m = (size_t)pair*TT + t;
            reinterpret_cast<float4*>(g_wc)[m*256 + tid] = acc[j];
            __nv_bfloat162 lo = __floats2bfloat162_rn(acc[j].x, acc[j].y);
            __nv_bfloat162 hi = __floats2bfloat162_rn(acc[j].z, acc[j].w);
            __nv_bfloat162* dst = reinterpret_cast<__nv_bfloat162*>(
                g_cat + m*KK + DD + (size_t)tid*4);
            dst[0] = lo; dst[1] = hi;
        }
    }
}

// ---------------- similarity: score[i][c] += mean_t cos(cap, wc) ----------------
__global__ __launch_bounds__(256)
void sim_kernel(const float* __restrict__ cap, float* __restrict__ out, int addmode) {
    __shared__ float sbuf[TT];
    int tid = threadIdx.x, lane = tid & 31, w = tid >> 5;
    int pair = blockIdx.x, c = pair >> 5, i = pair & 31;
    const float4* capv = reinterpret_cast<const float4*>(cap);
    const float4* wcv  = reinterpret_cast<const float4*>(g_wc);
    for (int jt = 0; jt < 5; jt++) {
        int t = w + jt*8;
        size_t ca = ((size_t)(c*TT + t)) * 256;
        size_t wa = ((size_t)(pair*TT + t)) * 256;
        float dot = 0.f, na = 0.f, nb = 0.f;
        #pragma unroll
        for (int j = 0; j < 8; j++) {
            float4 a = capv[ca + j*32 + lane];
            float4 b = wcv[wa + j*32 + lane];
            dot += a.x*b.x + a.y*b.y + a.z*b.z + a.w*b.w;
            na  += a.x*a.x + a.y*a.y + a.z*a.z + a.w*a.w;
            nb  += b.x*b.x + b.y*b.y + b.z*b.z + b.w*b.w;
        }
        #pragma unroll
        for (int o = 16; o; o >>= 1) {
            dot += __shfl_xor_sync(0xffffffffu, dot, o);
            na  += __shfl_xor_sync(0xffffffffu, na, o);
            nb  += __shfl_xor_sync(0xffffffffu, nb, o);
        }
        if (lane == 0)
            sbuf[t] = dot / fmaxf(sqrtf(na) * sqrtf(nb), 1e-8f);
    }
    __syncthreads();
    if (tid == 0) {
        float s = 0.f;
        for (int t = 0; t < TT; t++) s += sbuf[t];
        s *= (1.0f / TT);
        size_t o = (size_t)i * CC + c;
        out[o] = addmode ? (out[o] + s) : s;
    }
}

// ---------------- gated-memory GEMM: q1 = cap*sig(g) + tanh(u)*(1-sig(g)) ----------------
// u = cat @ W_lin + b_lin ; g = cat @ W_gate + b_gate. Tile 128M x 64N, dual weights.
__global__ __launch_bounds__(256)
void gemm_gated(const float* __restrict__ bl, const float* __restrict__ bg,
                const float* __restrict__ cap) {
    __shared__ __align__(16) __nv_bfloat16 As[2][128*PITCH];
    __shared__ __align__(16) __nv_bfloat16 Bs[2][2][64*PITCH];
    int tid = threadIdx.x, lane = tid & 31, wid = tid >> 5;
    int warp_m = wid & 3, warp_n = wid >> 2;       // 4 x 2 warp grid
    int gq = lane >> 2, tg = lane & 3;
    int ntile = blockIdx.x, mtile = blockIdx.y;

    float aL[2][4][4], aG[2][4][4];
    #pragma unroll
    for (int mf = 0; mf < 2; mf++)
        #pragma unroll
        for (int nf = 0; nf < 4; nf++)
            #pragma unroll
            for (int q = 0; q < 4; q++) { aL[mf][nf][q] = 0.f; aG[mf][nf][q] = 0.f; }

    // load-index precompute
    int a_r0 = tid >> 2,        a_c0 = tid & 3;
    int a_r1 = (tid + 256) >> 2, a_c1 = tid & 3;   // rows 64..127
    int b_r  = tid >> 2,        b_c  = tid & 3;
    const __nv_bfloat16* Asrc0 = g_cat + ((size_t)(mtile*128 + a_r0))*KK + a_c0*8;
    const __nv_bfloat16* Asrc1 = g_cat + ((size_t)(mtile*128 + a_r1))*KK + a_c1*8;
    const __nv_bfloat16* BsrcL = g_WtL + ((size_t)(ntile*64 + b_r))*KK + b_c*8;
    const __nv_bfloat16* BsrcG = g_WtG + ((size_t)(ntile*64 + b_r))*KK + b_c*8;
    uint32_t Adst0[2], Adst1[2], BdstL[2], BdstG[2];
    #pragma unroll
    for (int b = 0; b < 2; b++) {
        Adst0[b] = smem_u32(&As[b][a_r0*PITCH + a_c0*8]);
        Adst1[b] = smem_u32(&As[b][a_r1*PITCH + a_c1*8]);
        BdstL[b] = smem_u32(&Bs[b][0][b_r*PITCH + b_c*8]);
        BdstG[b] = smem_u32(&Bs[b][1][b_r*PITCH + b_c*8]);
    }

    // prefetch stage 0
    cpa16(Adst0[0], Asrc0); cpa16(Adst1[0], Asrc1);
    cpa16(BdstL[0], BsrcL); cpa16(BdstG[0], BsrcG);
    cpa_commit();

    for (int s = 0; s < 64; s++) {
        cpa_wait0();
        __syncthreads();
        if (s + 1 < 64) {
            int nb = (s + 1) & 1;
            int k0 = (s + 1) * 32;
            cpa16(Adst0[nb], Asrc0 + k0); cpa16(Adst1[nb], Asrc1 + k0);
            cpa16(BdstL[nb], BsrcL + k0); cpa16(BdstG[nb], BsrcG + k0);
            cpa_commit();
        }
        int buf = s & 1;
        const uint32_t* A32 = reinterpret_cast<const uint32_t*>(&As[buf][0]);
        const uint32_t* BL  = reinterpret_cast<const uint32_t*>(&Bs[buf][0][0]);
        const uint32_t* BG  = reinterpret_cast<const uint32_t*>(&Bs[buf][1][0]);
        #pragma unroll
        for (int kk = 0; kk < 2; kk++) {
            int kw = kk * 8;   // uint32 offset for k = kk*16
            uint32_t afr[2][4];
            #pragma unroll
            for (int mf = 0; mf < 2; mf++) {
                int mo = warp_m*32 + mf*16;
                afr[mf][0] = A32[(mo + gq)     * 20 + kw + tg];
                afr[mf][1] = A32[(mo + gq + 8) * 20 + kw + tg];
                afr[mf][2] = A32[(mo + gq)     * 20 + kw + tg + 4];
                afr[mf][3] = A32[(mo + gq + 8) * 20 + kw + tg + 4];
            }
            uint32_t bfL[4][2], bfG[4][2];
            #pragma unroll
            for (int nf = 0; nf < 4; nf++) {
                int no = warp_n*32 + nf*8;
                bfL[nf][0] = BL[(no + gq) * 20 + kw + tg];
                bfL[nf][1] = BL[(no + gq) * 20 + kw + tg + 4];
                bfG[nf][0] = BG[(no + gq) * 20 + kw + tg];
                bfG[nf][1] = BG[(no + gq) * 20 + kw + tg + 4];
            }
            #pragma unroll
            for (int mf = 0; mf < 2; mf++)
                #pragma unroll
                for (int nf = 0; nf < 4; nf++) {
                    MMA16816(aL[mf][nf], afr[mf], bfL[nf]);
                    MMA16816(aG[mf][nf], afr[mf], bfG[nf]);
                }
        }
    }

    // fused epilogue
    #pragma unroll
    for (int mf = 0; mf < 2; mf++) {
        #pragma unroll
        for (int nf = 0; nf < 4; nf++) {
            int rb = mtile*128 + warp_m*32 + mf*16 + gq;
            int cb = ntile*64 + warp_n*32 + nf*8 + tg*2;
            float2 bl2 = *reinterpret_cast<const float2*>(bl + cb);
            float2 bg2 = *reinterpret_cast<const float2*>(bg + cb);
            #pragma unroll
            for (int h = 0; h < 2; h++) {
                int r = rb + h*8;
                int cc = r / (II*TT), t = r % TT;
                float2 cp = *reinterpret_cast<const float2*>(
                    cap + (((size_t)(cc*TT + t)) << 10) + cb);
                float u0 = tanhf(aL[mf][nf][h*2 + 0] + bl2.x);
                float u1 = tanhf(aL[mf][nf][h*2 + 1] + bl2.y);
                float s0 = 1.f / (1.f + expf(-(aG[mf][nf][h*2 + 0] + bg2.x)));
                float s1 = 1.f / (1.f + expf(-(aG[mf][nf][h*2 + 1] + bg2.y)));
                float2 o;
                o.x = cp.x * s0 + u0 * (1.f - s0);
                o.y = cp.y * s1 + u1 * (1.f - s1);
                *reinterpret_cast<float2*>(g_q1 + (size_t)r * DD + cb) = o;
            }
        }
    }
}

// ---------------- launch ----------------
extern "C" void kernel_launch(void* const* d_in, const int* in_sizes, int n_in,
                              void* d_out, int out_size) {
    (void)in_sizes; (void)n_in; (void)out_size;
    const float* img    = (const float*)d_in[0];
    const float* cap    = (const float*)d_in[1];
    const float* W_lin  = (const float*)d_in[2];
    const float* b_lin  = (const float*)d_in[3];
    const float* W_gate = (const float*)d_in[4];
    const float* b_gate = (const float*)d_in[5];
    float* out = (float*)d_out;

    const int SMEM_ATTN = (RR*DD + RR*TT + TT*RR) * (int)sizeof(float);  // 158976
    cudaFuncSetAttribute(attn_kernel, cudaFuncAttributeMaxDynamicSharedMemorySize, SMEM_ATTN);

    prep_wt<<<dim3(32, 64), dim3(32, 8)>>>(W_lin, 0);
    prep_wt<<<dim3(32, 64), dim3(32, 8)>>>(W_gate, 1);
    prep_catL<<<MM, 256>>>(cap);

    // iteration 0
    attn_kernel<<<CC*II, 256, SMEM_ATTN>>>(img, cap, 0);
    sim_kernel<<<CC*II, 256>>>(cap, out, 0);

    // gated memory (only live once: iteration 1's update is dead code)
    gemm_gated<<<dim3(16, 320), 256>>>(b_lin, b_gate, cap);

    // iteration 1
    attn_kernel<<<CC*II, 256, SMEM_ATTN>>>(img, cap, 1);
    sim_kernel<<<CC*II, 256>>>(cap, out, 1);
}

// round 11
// speedup vs baseline: 1.0012x; 1.0012x over previous
#include <cuda_runtime.h>
#include <cuda_bf16.h>
#include <cstdint>
#include <math.h>

#define CC 32
#define II 32
#define TT 40
#define RR 36
#define DD 1024
#define MM (CC*II*TT)     /* 40960 */
#define KK 2048
#define PITCH 40          /* bf16 elems per smem row (32 data + 8 pad) */

// ---------------- device scratch (no cudaMalloc allowed) ----------------
__device__ float g_wc[(size_t)MM*DD];                 // weightedContext fp32
__device__ float g_q1[(size_t)MM*DD];                 // updated query
__device__ __nv_bfloat16 g_cat[(size_t)MM*KK];        // [query | wc] bf16
__device__ __nv_bfloat16 g_WtL[(size_t)DD*KK];        // W_lin^T  [n][k]
__device__ __nv_bfloat16 g_WtG[(size_t)DD*KK];        // W_gate^T [n][k]

// ---------------- helpers ----------------
__device__ __forceinline__ uint32_t smem_u32(const void* p) {
    uint32_t a;
    asm("{ .reg .u64 t; cvta.to.shared.u64 t, %1; cvt.u32.u64 %0, t; }" : "=r"(a) : "l"(p));
    return a;
}
__device__ __forceinline__ void cpa16(uint32_t d, const void* s) {
    asm volatile("cp.async.cg.shared.global [%0], [%1], 16;" :: "r"(d), "l"(s));
}
__device__ __forceinline__ void cpa_commit() { asm volatile("cp.async.commit_group;" ::: "memory"); }
__device__ __forceinline__ void cpa_wait0()  { asm volatile("cp.async.wait_group 0;" ::: "memory"); }

#define MMA16816(d, a, b) \
  asm volatile("mma.sync.aligned.m16n8k16.row.col.f32.bf16.bf16.f32 " \
    "{%0,%1,%2,%3}, {%4,%5,%6,%7}, {%8,%9}, {%0,%1,%2,%3};" \
    : "+f"((d)[0]), "+f"((d)[1]), "+f"((d)[2]), "+f"((d)[3]) \
    : "r"((a)[0]), "r"((a)[1]), "r"((a)[2]), "r"((a)[3]), "r"((b)[0]), "r"((b)[1]))

// ---------------- prep: W^T -> bf16 ----------------
__global__ void prep_wt(const float* __restrict__ W, int which) {
    __shared__ float tile[32][33];
    __nv_bfloat16* Wt = which ? g_WtG : g_WtL;
    int n0 = blockIdx.x * 32;   // 32 tiles
    int k0 = blockIdx.y * 32;   // 64 tiles
    int tx = threadIdx.x, ty = threadIdx.y;  // (32, 8)
    #pragma unroll
    for (int j = 0; j < 4; j++)
        tile[ty + j*8][tx] = W[(size_t)(k0 + ty + j*8) * DD + n0 + tx];
    __syncthreads();
    #pragma unroll
    for (int j = 0; j < 4; j++)
        Wt[(size_t)(n0 + ty + j*8) * KK + k0 + tx] =
            __float2bfloat16(tile[tx][ty + j*8]);
}

// ---------------- prep: cat left half = broadcast caption (bf16) ----------------
__global__ void prep_catL(const float* __restrict__ cap) {
    size_t idx = (size_t)blockIdx.x * 256 + threadIdx.x;   // f4 index in [0, MM*256)
    int m  = (int)(idx >> 8);
    int dv = (int)(idx & 255);
    int c = m / (II*TT), t = m % TT;
    float4 v = reinterpret_cast<const float4*>(cap)[((size_t)(c*TT + t) << 8) + dv];
    __nv_bfloat162 lo = __floats2bfloat162_rn(v.x, v.y);
    __nv_bfloat162 hi = __floats2bfloat162_rn(v.z, v.w);
    __nv_bfloat162* dst = reinterpret_cast<__nv_bfloat162*>(g_cat + (size_t)m*KK + (size_t)dv*4);
    dst[0] = lo; dst[1] = hi;
}

// ---------------- fused attention step ----------------
// attn = leaky(ctx @ q^T); l2norm over t; softmax_r(9*attn^T); wc = attn @ ctx
__global__ __launch_bounds__(256)
void attn_kernel(const float* __restrict__ img, const float* __restrict__ cap, int iter) {
    extern __shared__ float sm[];
    float4* img4 = reinterpret_cast<float4*>(sm);   // 36*256 float4
    float* attn  = sm + RR*DD;                      // [36][40]  (r-major)
    float* attn2 = attn + RR*TT;                    // [40][36]  (t-major, softmaxed)
    int tid = threadIdx.x, lane = tid & 31, w = tid >> 5;
    int pair = blockIdx.x, c = pair >> 5, i = pair & 31;

    // load image region tile into smem
    const float4* imgv = reinterpret_cast<const float4*>(img) + (size_t)i * RR * 256;
    #pragma unroll
    for (int j = 0; j < 36; j++)
        img4[j*256 + tid] = imgv[j*256 + tid];
    __syncthreads();

    // phase B: dot products, Q rows in registers (2 t-rows per pass)
    const float4* qv = iter ? reinterpret_cast<const float4*>(g_q1)
                            : reinterpret_cast<const float4*>(cap);
    for (int base = 0; base < 48; base += 16) {
        int tA = base + w;
        int tB = base + 8 + w;
        bool hasB = (base < 32);
        int rA = iter ? (pair*TT + tA) : (c*TT + tA);
        size_t qa = (size_t)rA * 256;
        float4 Qa[8], Qb[8];
        #pragma unroll
        for (int j = 0; j < 8; j++) Qa[j] = qv[qa + j*32 + lane];
        if (hasB) {
            int rB = iter ? (pair*TT + tB) : (c*TT + tB);
            size_t qb = (size_t)rB * 256;
            #pragma unroll
            for (int j = 0; j < 8; j++) Qb[j] = qv[qb + j*32 + lane];
        }
        for (int r = 0; r < RR; r++) {
            float pa = 0.f, pb = 0.f;
            #pragma unroll
            for (int j = 0; j < 8; j++) {
                float4 v = img4[r*256 + j*32 + lane];
                pa += v.x*Qa[j].x + v.y*Qa[j].y + v.z*Qa[j].z + v.w*Qa[j].w;
                if (hasB) pb += v.x*Qb[j].x + v.y*Qb[j].y + v.z*Qb[j].z + v.w*Qb[j].w;
            }
            #pragma unroll
            for (int o = 16; o; o >>= 1) {
                pa += __shfl_xor_sync(0xffffffffu, pa, o);
                pb += __shfl_xor_sync(0xffffffffu, pb, o);
            }
            if (lane == 0) {
                attn[r*TT + tA] = pa;
                if (hasB) attn[r*TT + tB] = pb;
            }
        }
    }
    __syncthreads();

    // phase C: leaky relu + l2norm over t (per r)
    if (tid < RR) {
        float s = 0.f;
        #pragma unroll 8
        for (int t = 0; t < TT; t++) {
            float v = attn[tid*TT + t];
            v = (v > 0.f) ? v : 0.1f * v;
            attn[tid*TT + t] = v;
            s += v * v;
        }
        float inv = 1.f / (sqrtf(s) + 1e-8f);
        #pragma unroll 8
        for (int t = 0; t < TT; t++) attn[tid*TT + t] *= inv;
    }
    __syncthreads();

    // phase D: softmax over r (per t), temperature 9
    if (tid < TT) {
        float mx = -1e30f;
        for (int r = 0; r < RR; r++) mx = fmaxf(mx, attn[r*TT + tid]);
        float s = 0.f;
        for (int r = 0; r < RR; r++) {
            float e = expf(9.0f * (attn[r*TT + tid] - mx));
            attn2[tid*RR + r] = e;
            s += e;
        }
        float inv = 1.f / s;
        for (int r = 0; r < RR; r++) attn2[tid*RR + r] *= inv;
    }
    __syncthreads();

    // phase E: wc[t][d] = sum_r attn2[t][r] * img[r][d]; write fp32 + bf16(cat right)
    for (int tb = 0; tb < 5; tb++) {
        float4 acc[8];
        #pragma unroll
        for (int j = 0; j < 8; j++) acc[j] = make_float4(0.f, 0.f, 0.f, 0.f);
        for (int r = 0; r < RR; r++) {
            float4 v = img4[r*256 + tid];
            #pragma unroll
            for (int j = 0; j < 8; j++) {
                float a = attn2[(tb*8 + j)*RR + r];
                acc[j].x += v.x*a; acc[j].y += v.y*a;
                acc[j].z += v.z*a; acc[j].w += v.w*a;
            }
        }
        #pragma unroll
        for (int j = 0; j < 8; j++) {
            int t = tb*8 + j;
            size_t m = (size_t)pair*TT + t;
            reinterpret_cast<float4*>(g_wc)[m*256 + tid] = acc[j];
            __nv_bfloat162 lo = __floats2bfloat162_rn(acc[j].x, acc[j].y);
            __nv_bfloat162 hi = __floats2bfloat162_rn(acc[j].z, acc[j].w);
            __nv_bfloat162* dst = reinterpret_cast<__nv_bfloat162*>(
                g_cat + m*KK + DD + (size_t)tid*4);
            dst[0] = lo; dst[1] = hi;
        }
    }
}

// ---------------- similarity: score[i][c] += mean_t cos(cap, wc) ----------------
__global__ __launch_bounds__(256)
void sim_kernel(const float* __restrict__ cap, float* __restrict__ out, int addmode) {
    __shared__ float sbuf[TT];
    int tid = threadIdx.x, lane = tid & 31, w = tid >> 5;
    int pair = blockIdx.x, c = pair >> 5, i = pair & 31;
    const float4* capv = reinterpret_cast<const float4*>(cap);
    const float4* wcv  = reinterpret_cast<const float4*>(g_wc);
    for (int jt = 0; jt < 5; jt++) {
        int t = w + jt*8;
        size_t ca = ((size_t)(c*TT + t)) * 256;
        size_t wa = ((size_t)(pair*TT + t)) * 256;
        float dot = 0.f, na = 0.f, nb = 0.f;
        #pragma unroll
        for (int j = 0; j < 8; j++) {
            float4 a = capv[ca + j*32 + lane];
            float4 b = wcv[wa + j*32 + lane];
            dot += a.x*b.x + a.y*b.y + a.z*b.z + a.w*b.w;
            na  += a.x*a.x + a.y*a.y + a.z*a.z + a.w*a.w;
            nb  += b.x*b.x + b.y*b.y + b.z*b.z + b.w*b.w;
        }
        #pragma unroll
        for (int o = 16; o; o >>= 1) {
            dot += __shfl_xor_sync(0xffffffffu, dot, o);
            na  += __shfl_xor_sync(0xffffffffu, na, o);
            nb  += __shfl_xor_sync(0xffffffffu, nb, o);
        }
        if (lane == 0)
            sbuf[t] = dot / fmaxf(sqrtf(na) * sqrtf(nb), 1e-8f);
    }
    __syncthreads();
    if (tid == 0) {
        float s = 0.f;
        for (int t = 0; t < TT; t++) s += sbuf[t];
        s *= (1.0f / TT);
        size_t o = (size_t)i * CC + c;
        out[o] = addmode ? (out[o] + s) : s;
    }
}

// ---------------- gated-memory GEMM: q1 = cap*sig(g) + tanh(u)*(1-sig(g)) ----------------
// u = cat @ W_lin + b_lin ; g = cat @ W_gate + b_gate. Tile 128M x 64N, dual weights.
__global__ __launch_bounds__(256)
void gemm_gated(const float* __restrict__ bl, const float* __restrict__ bg,
                const float* __restrict__ cap) {
    __shared__ __align__(16) __nv_bfloat16 As[2][128*PITCH];
    __shared__ __align__(16) __nv_bfloat16 Bs[2][2][64*PITCH];
    int tid = threadIdx.x, lane = tid & 31, wid = tid >> 5;
    int warp_m = wid & 3, warp_n = wid >> 2;       // 4 x 2 warp grid
    int gq = lane >> 2, tg = lane & 3;
    int ntile = blockIdx.x, mtile = blockIdx.y;

    float aL[2][4][4], aG[2][4][4];
    #pragma unroll
    for (int mf = 0; mf < 2; mf++)
        #pragma unroll
        for (int nf = 0; nf < 4; nf++)
            #pragma unroll
            for (int q = 0; q < 4; q++) { aL[mf][nf][q] = 0.f; aG[mf][nf][q] = 0.f; }

    // load-index precompute
    int a_r0 = tid >> 2,        a_c0 = tid & 3;
    int a_r1 = (tid + 256) >> 2, a_c1 = tid & 3;   // rows 64..127
    int b_r  = tid >> 2,        b_c  = tid & 3;
    const __nv_bfloat16* Asrc0 = g_cat + ((size_t)(mtile*128 + a_r0))*KK + a_c0*8;
    const __nv_bfloat16* Asrc1 = g_cat + ((size_t)(mtile*128 + a_r1))*KK + a_c1*8;
    const __nv_bfloat16* BsrcL = g_WtL + ((size_t)(ntile*64 + b_r))*KK + b_c*8;
    const __nv_bfloat16* BsrcG = g_WtG + ((size_t)(ntile*64 + b_r))*KK + b_c*8;
    uint32_t Adst0[2], Adst1[2], BdstL[2], BdstG[2];
    #pragma unroll
    for (int b = 0; b < 2; b++) {
        Adst0[b] = smem_u32(&As[b][a_r0*PITCH + a_c0*8]);
        Adst1[b] = smem_u32(&As[b][a_r1*PITCH + a_c1*8]);
        BdstL[b] = smem_u32(&Bs[b][0][b_r*PITCH + b_c*8]);
        BdstG[b] = smem_u32(&Bs[b][1][b_r*PITCH + b_c*8]);
    }

    // prefetch stage 0
    cpa16(Adst0[0], Asrc0); cpa16(Adst1[0], Asrc1);
    cpa16(BdstL[0], BsrcL); cpa16(BdstG[0], BsrcG);
    cpa_commit();

    for (int s = 0; s < 64; s++) {
        cpa_wait0();
        __syncthreads();
        if (s + 1 < 64) {
            int nb = (s + 1) & 1;
            int k0 = (s + 1) * 32;
            cpa16(Adst0[nb], Asrc0 + k0); cpa16(Adst1[nb], Asrc1 + k0);
            cpa16(BdstL[nb], BsrcL + k0); cpa16(BdstG[nb], BsrcG + k0);
            cpa_commit();
        }
        int buf = s & 1;
        const uint32_t* A32 = reinterpret_cast<const uint32_t*>(&As[buf][0]);
        const uint32_t* BL  = reinterpret_cast<const uint32_t*>(&Bs[buf][0][0]);
        const uint32_t* BG  = reinterpret_cast<const uint32_t*>(&Bs[buf][1][0]);
        #pragma unroll
        for (int kk = 0; kk < 2; kk++) {
            int kw = kk * 8;   // uint32 offset for k = kk*16
            uint32_t afr[2][4];
            #pragma unroll
            for (int mf = 0; mf < 2; mf++) {
                int mo = warp_m*32 + mf*16;
                afr[mf][0] = A32[(mo + gq)     * 20 + kw + tg];
                afr[mf][1] = A32[(mo + gq + 8) * 20 + kw + tg];
                afr[mf][2] = A32[(mo + gq)     * 20 + kw + tg + 4];
                afr[mf][3] = A32[(mo + gq + 8) * 20 + kw + tg + 4];
            }
            uint32_t bfL[4][2], bfG[4][2];
            #pragma unroll
            for (int nf = 0; nf < 4; nf++) {
                int no = warp_n*32 + nf*8;
                bfL[nf][0] = BL[(no + gq) * 20 + kw + tg];
                bfL[nf][1] = BL[(no + gq) * 20 + kw + tg + 4];
                bfG[nf][0] = BG[(no + gq) * 20 + kw + tg];
                bfG[nf][1] = BG[(no + gq) * 20 + kw + tg + 4];
            }
            #pragma unroll
            for (int mf = 0; mf < 2; mf++)
                #pragma unroll
                for (int nf = 0; nf < 4; nf++) {
                    MMA16816(aL[mf][nf], afr[mf], bfL[nf]);
                    MMA16816(aG[mf][nf], afr[mf], bfG[nf]);
                }
        }
    }

    // fused epilogue
    #pragma unroll
    for (int mf = 0; mf < 2; mf++) {
        #pragma unroll
        for (int nf = 0; nf < 4; nf++) {
            int rb = mtile*128 + warp_m*32 + mf*16 + gq;
            int cb = ntile*64 + warp_n*32 + nf*8 + tg*2;
            float2 bl2 = *reinterpret_cast<const float2*>(bl + cb);
            float2 bg2 = *reinterpret_cast<const float2*>(bg + cb);
            #pragma unroll
            for (int h = 0; h < 2; h++) {
                int r = rb + h*8;
                int cc = r / (II*TT), t = r % TT;
                float2 cp = *reinterpret_cast<const float2*>(
                    cap + (((size_t)(cc*TT + t)) << 10) + cb);
                float u0 = tanhf(aL[mf][nf][h*2 + 0] + bl2.x);
                float u1 = tanhf(aL[mf][nf][h*2 + 1] + bl2.y);
                float s0 = 1.f / (1.f + expf(-(aG[mf][nf][h*2 + 0] + bg2.x)));
                float s1 = 1.f / (1.f + expf(-(aG[mf][nf][h*2 + 1] + bg2.y)));
                float2 o;
                o.x = cp.x * s0 + u0 * (1.f - s0);
                o.y = cp.y * s1 + u1 * (1.f - s1);
                *reinterpret_cast<float2*>(g_q1 + (size_t)r * DD + cb) = o;
            }
        }
    }
}

// ---------------- launch ----------------
extern "C" void kernel_launch(void* const* d_in, const int* in_sizes, int n_in,
                              void* d_out, int out_size) {
    (void)in_sizes; (void)n_in; (void)out_size;
    const float* img    = (const float*)d_in[0];
    const float* cap    = (const float*)d_in[1];
    const float* W_lin  = (const float*)d_in[2];
    const float* b_lin  = (const float*)d_in[3];
    const float* W_gate = (const float*)d_in[4];
    const float* b_gate = (const float*)d_in[5];
    float* out = (float*)d_out;

    const int SMEM_ATTN = (RR*DD + RR*TT + TT*RR) * (int)sizeof(float);  // 158976
    cudaFuncSetAttribute(attn_kernel, cudaFuncAttributeMaxDynamicSharedMemorySize, SMEM_ATTN);

    prep_wt<<<dim3(32, 64), dim3(32, 8)>>>(W_lin, 0);
    prep_wt<<<dim3(32, 64), dim3(32, 8)>>>(W_gate, 1);
    prep_catL<<<MM, 256>>>(cap);

    // iteration 0
    attn_kernel<<<CC*II, 256, SMEM_ATTN>>>(img, cap, 0);
    sim_kernel<<<CC*II, 256>>>(cap, out, 0);

    // gated memory (only live once: iteration 1's update is dead code)
    gemm_gated<<<dim3(16, 320), 256>>>(b_lin, b_gate, cap);

    // iteration 1
    attn_kernel<<<CC*II, 256, SMEM_ATTN>>>(img, cap, 1);
    sim_kernel<<<CC*II, 256>>>(cap, out, 1);
}